// round 6
// baseline (speedup 1.0000x reference)
#include <cuda_runtime.h>
#include <cuda_bf16.h>
#include <cstdint>

// out = x @ W,  W = m + softplus(s) * mean_k(eps)
// Single fused kernel, 144 co-resident CTAs:
//   CTAs [64,144): producers — split x to bf16 hi/lo, build W hi/lo per k-row,
//                  publish per-chunk flags (8 chunks x 128 k-rows).
//   CTAs [0,64):   consumers — 64x256 output tile each, HMMA bf16 3-split
//                  GEMM consuming chunks as they become ready.

#define B_DIM 1024
#define IN_DIM 1024
#define OUT_DIM 1024
#define K_SAMPLES 100
#define PLANE ((IN_DIM * OUT_DIM) / 4)

#define N_CONS 64
#define N_PROD 80
#define GRID_TOTAL (N_CONS + N_PROD)
#define NCHUNK 8                      // 128 k-rows per chunk

__device__ __nv_bfloat16 d_xhi[B_DIM * IN_DIM];
__device__ __nv_bfloat16 d_xlo[B_DIM * IN_DIM];
__device__ __nv_bfloat16 d_whi[IN_DIM * OUT_DIM];   // [k][n]
__device__ __nv_bfloat16 d_wlo[IN_DIM * OUT_DIM];
__device__ int g_flags[16];   // [0]=x rows done (1024), [1..8]=W rows per chunk (128)

// ---------------------------------------------------------------------------
// helpers
// ---------------------------------------------------------------------------
__device__ __forceinline__ uint32_t smem_u32(const void* p) {
    uint32_t a;
    asm("{ .reg .u64 t; cvta.to.shared.u64 t, %1; cvt.u32.u64 %0, t; }"
        : "=r"(a) : "l"(p));
    return a;
}
__device__ __forceinline__ void cp16(uint32_t dst, const void* src) {
    asm volatile("cp.async.cg.shared.global [%0], [%1], 16;"
                 :: "r"(dst), "l"(__cvta_generic_to_global(src)) : "memory");
}
__device__ __forceinline__ void ldm4(uint32_t addr, uint32_t r[4]) {
    asm volatile("ldmatrix.sync.aligned.m8n8.x4.shared.b16 {%0,%1,%2,%3}, [%4];"
                 : "=r"(r[0]), "=r"(r[1]), "=r"(r[2]), "=r"(r[3]) : "r"(addr));
}
__device__ __forceinline__ void ldm4t(uint32_t addr, uint32_t r[4]) {
    asm volatile("ldmatrix.sync.aligned.m8n8.x4.trans.shared.b16 {%0,%1,%2,%3}, [%4];"
                 : "=r"(r[0]), "=r"(r[1]), "=r"(r[2]), "=r"(r[3]) : "r"(addr));
}
__device__ __forceinline__ void mma_bf16(float c[4], const uint32_t a[4],
                                         const uint32_t b[2]) {
    asm volatile(
        "mma.sync.aligned.m16n8k16.row.col.f32.bf16.bf16.f32 "
        "{%0,%1,%2,%3}, {%4,%5,%6,%7}, {%8,%9}, {%0,%1,%2,%3};"
        : "+f"(c[0]), "+f"(c[1]), "+f"(c[2]), "+f"(c[3])
        : "r"(a[0]), "r"(a[1]), "r"(a[2]), "r"(a[3]), "r"(b[0]), "r"(b[1]));
}
__device__ __forceinline__ void wait_flag(int idx, int target) {
    volatile int* f = &g_flags[idx];
    while (*f < target) {}
    __threadfence();
}
__device__ __forceinline__ void split_store(__nv_bfloat16* hi, __nv_bfloat16* lo,
                                            int idx4, float4 v) {
    __nv_bfloat16 h0 = __float2bfloat16_rn(v.x);
    __nv_bfloat16 h1 = __float2bfloat16_rn(v.y);
    __nv_bfloat16 h2 = __float2bfloat16_rn(v.z);
    __nv_bfloat16 h3 = __float2bfloat16_rn(v.w);
    __nv_bfloat16 l0 = __float2bfloat16_rn(v.x - __bfloat162float(h0));
    __nv_bfloat16 l1 = __float2bfloat16_rn(v.y - __bfloat162float(h1));
    __nv_bfloat16 l2 = __float2bfloat16_rn(v.z - __bfloat162float(h2));
    __nv_bfloat16 l3 = __float2bfloat16_rn(v.w - __bfloat162float(h3));
    __nv_bfloat162* hp = reinterpret_cast<__nv_bfloat162*>(hi) + idx4 * 2;
    __nv_bfloat162* lp = reinterpret_cast<__nv_bfloat162*>(lo) + idx4 * 2;
    hp[0] = __nv_bfloat162(h0, h1);
    hp[1] = __nv_bfloat162(h2, h3);
    lp[0] = __nv_bfloat162(l0, l1);
    lp[1] = __nv_bfloat162(l2, l3);
}

#define ADD4(a, b) { (a).x += (b).x; (a).y += (b).y; (a).z += (b).z; (a).w += (b).w; }

// ---------------------------------------------------------------------------
// Producer: x split, then W rows with per-chunk flags
// ---------------------------------------------------------------------------
__device__ void producer(int p, const float4* __restrict__ x,
                         const float4* __restrict__ eps,
                         const float4* __restrict__ wm,
                         const float4* __restrict__ ws) {
    const int t = threadIdx.x;

    int nx = 0;
    for (int r = p; r < B_DIM; r += N_PROD) {
        const int idx = r * 256 + t;
        split_store(d_xhi, d_xlo, idx, x[idx]);
        nx++;
    }
    __threadfence();
    __syncthreads();
    if (t == 0 && nx) atomicAdd(&g_flags[0], nx);

    const float inv_k = 1.0f / (float)K_SAMPLES;
    for (int r = p; r < IN_DIM; r += N_PROD) {
        const int idx = r * 256 + t;
        const float4* pp = eps + idx;
        float4 s0 = make_float4(0.f, 0.f, 0.f, 0.f);
        float4 s1 = s0;
#pragma unroll 1
        for (int k = 0; k < K_SAMPLES; k += 10) {
            float4 e0 = pp[(k + 0) * PLANE];
            float4 e1 = pp[(k + 1) * PLANE];
            float4 e2 = pp[(k + 2) * PLANE];
            float4 e3 = pp[(k + 3) * PLANE];
            float4 e4 = pp[(k + 4) * PLANE];
            float4 e5 = pp[(k + 5) * PLANE];
            float4 e6 = pp[(k + 6) * PLANE];
            float4 e7 = pp[(k + 7) * PLANE];
            float4 e8 = pp[(k + 8) * PLANE];
            float4 e9 = pp[(k + 9) * PLANE];
            ADD4(e0, e2); ADD4(e4, e6); ADD4(e0, e8); ADD4(e0, e4); ADD4(s0, e0);
            ADD4(e1, e3); ADD4(e5, e7); ADD4(e1, e9); ADD4(e1, e5); ADD4(s1, e1);
        }
        ADD4(s0, s1);

        float4 m4 = wm[idx];
        float4 s4 = ws[idx];
        float sp_x = fmaxf(s4.x, 0.f) + log1pf(expf(-fabsf(s4.x)));
        float sp_y = fmaxf(s4.y, 0.f) + log1pf(expf(-fabsf(s4.y)));
        float sp_z = fmaxf(s4.z, 0.f) + log1pf(expf(-fabsf(s4.z)));
        float sp_w = fmaxf(s4.w, 0.f) + log1pf(expf(-fabsf(s4.w)));

        float4 w4;
        w4.x = fmaf(sp_x, s0.x * inv_k, m4.x);
        w4.y = fmaf(sp_y, s0.y * inv_k, m4.y);
        w4.z = fmaf(sp_z, s0.z * inv_k, m4.z);
        w4.w = fmaf(sp_w, s0.w * inv_k, m4.w);

        split_store(d_whi, d_wlo, idx, w4);

        __threadfence();
        __syncthreads();
        if (t == 0) atomicAdd(&g_flags[1 + (r >> 7)], 1);
    }
}

// ---------------------------------------------------------------------------
// Consumer: 64x256 tile, BKT=32, 3-stage cp.async, chunk-gated
// ---------------------------------------------------------------------------
#define BM 64
#define BN 256
#define BKT 32
#define NKT (IN_DIM / BKT)            // 32 (4 per chunk)
#define NSTAGE 3
#define RSA 80                        // A row stride bytes (40 elems)
#define RSB 528                       // B row stride bytes (264 elems)
#define OFF_AH 0
#define OFF_AL (BM * RSA)                     // 5120
#define OFF_BH (2 * BM * RSA)                 // 10240
#define OFF_BL (OFF_BH + BKT * RSB)           // 27136
#define STAGE_BYTES (OFF_BH + 2 * BKT * RSB)  // 44032
#define FUSED_SMEM (NSTAGE * STAGE_BYTES)     // 132096

__device__ __forceinline__ void load_stage(uint32_t st, int bm, int bn,
                                           int k0, int tid) {
    {   // A: 64 rows x 32 k, hi+lo
        const int row = tid >> 2;
        const int ch = tid & 3;
        const int gk = k0 + ch * 8;
        cp16(st + OFF_AH + row * RSA + ch * 16, d_xhi + (bm + row) * IN_DIM + gk);
        cp16(st + OFF_AL + row * RSA + ch * 16, d_xlo + (bm + row) * IN_DIM + gk);
    }
    {   // B: 32 k-rows x 256 n, hi+lo, [k][n]
        const int row = tid >> 3;
        const int ch = tid & 7;
        const __nv_bfloat16* sh = d_whi + (k0 + row) * OUT_DIM + bn;
        const __nv_bfloat16* sl = d_wlo + (k0 + row) * OUT_DIM + bn;
#pragma unroll
        for (int i = 0; i < 4; i++) {
            const int c = ch + 8 * i;
            cp16(st + OFF_BH + row * RSB + c * 16, sh + c * 8);
            cp16(st + OFF_BL + row * RSB + c * 16, sl + c * 8);
        }
    }
}

__device__ void consumer(int cid, float* __restrict__ out, char* smem) {
    const uint32_t sbase = smem_u32(smem);
    const int tid = threadIdx.x;
    const int lane = tid & 31;
    const int wid = tid >> 5;
    const int wm = wid & 1;          // 32-row half
    const int wn = wid >> 1;         // 64-col quarter

    const int bm = (cid >> 2) * BM;
    const int bn = (cid & 3) * BN;

    float acc[2][8][4];
#pragma unroll
    for (int i = 0; i < 2; i++)
#pragma unroll
        for (int j = 0; j < 8; j++)
#pragma unroll
            for (int k = 0; k < 4; k++) acc[i][j][k] = 0.f;

    const int ar = lane & 15;
    const int ak = (lane >> 4) * 8;
    const int bkr = (lane & 7) + ((lane >> 3) & 1) * 8;
    const int bnc = (lane >> 4) * 8;

    wait_flag(0, B_DIM);             // x fully split
    wait_flag(1, 128);               // chunk 0 of W ready
    int ready = 0;

#pragma unroll
    for (int s = 0; s < NSTAGE - 1; s++) {   // k-tiles 0,1 — chunk 0
        load_stage(sbase + s * STAGE_BYTES, bm, bn, s * BKT, tid);
        asm volatile("cp.async.commit_group;" ::: "memory");
    }

#pragma unroll 1
    for (int t = 0; t < NKT; ++t) {
        if (t <= NKT - NSTAGE)
            asm volatile("cp.async.wait_group %0;" :: "n"(NSTAGE - 2) : "memory");
        else
            asm volatile("cp.async.wait_group 0;" ::: "memory");
        __syncthreads();

        if (t + NSTAGE - 1 < NKT) {
            const int c = (t + NSTAGE - 1) >> 2;
            if (c > ready) { wait_flag(1 + c, 128); ready = c; }
            load_stage(sbase + ((t + NSTAGE - 1) % NSTAGE) * STAGE_BYTES,
                       bm, bn, (t + NSTAGE - 1) * BKT, tid);
            asm volatile("cp.async.commit_group;" ::: "memory");
        }

        const uint32_t st = sbase + (t % NSTAGE) * STAGE_BYTES;

#pragma unroll
        for (int ks = 0; ks < 2; ks++) {
            uint32_t ah[2][4], al[2][4], bh[8][2], bl[8][2];
#pragma unroll
            for (int mh = 0; mh < 2; mh++) {
                const int row = wm * 32 + mh * 16 + ar;
                const uint32_t ad = st + OFF_AH + row * RSA + (ks * 16 + ak) * 2;
                ldm4(ad, ah[mh]);
                ldm4(ad + (OFF_AL - OFF_AH), al[mh]);
            }
#pragma unroll
            for (int q = 0; q < 4; q++) {
                const int krow = ks * 16 + bkr;
                const int ncol = wn * 64 + q * 16 + bnc;
                const uint32_t bd = st + OFF_BH + krow * RSB + ncol * 2;
                uint32_t tmp[4];
                ldm4t(bd, tmp);
                bh[2 * q][0] = tmp[0]; bh[2 * q][1] = tmp[1];
                bh[2 * q + 1][0] = tmp[2]; bh[2 * q + 1][1] = tmp[3];
                ldm4t(bd + (OFF_BL - OFF_BH), tmp);
                bl[2 * q][0] = tmp[0]; bl[2 * q][1] = tmp[1];
                bl[2 * q + 1][0] = tmp[2]; bl[2 * q + 1][1] = tmp[3];
            }
#pragma unroll
            for (int mh = 0; mh < 2; mh++)
#pragma unroll
                for (int nf = 0; nf < 8; nf++) {
                    mma_bf16(acc[mh][nf], ah[mh], bh[nf]);
                    mma_bf16(acc[mh][nf], ah[mh], bl[nf]);
                    mma_bf16(acc[mh][nf], al[mh], bh[nf]);
                }
        }
    }

    const int crow = lane >> 2;
    const int ccol = (lane & 3) * 2;
#pragma unroll
    for (int mh = 0; mh < 2; mh++) {
#pragma unroll
        for (int nf = 0; nf < 8; nf++) {
            const int row = bm + wm * 32 + mh * 16 + crow;
            const int col = bn + wn * 64 + nf * 8 + ccol;
            *reinterpret_cast<float2*>(&out[row * OUT_DIM + col]) =
                make_float2(acc[mh][nf][0], acc[mh][nf][1]);
            *reinterpret_cast<float2*>(&out[(row + 8) * OUT_DIM + col]) =
                make_float2(acc[mh][nf][2], acc[mh][nf][3]);
        }
    }
}

// ---------------------------------------------------------------------------
__global__ __launch_bounds__(256, 1)
void fused_kernel(const float4* __restrict__ x, const float4* __restrict__ eps,
                  const float4* __restrict__ wm, const float4* __restrict__ ws,
                  float* __restrict__ out) {
    extern __shared__ char smem[];
    if (blockIdx.x < N_CONS)
        consumer(blockIdx.x, out, smem);
    else
        producer(blockIdx.x - N_CONS, x, eps, wm, ws);
}

extern "C" void kernel_launch(void* const* d_in, const int* in_sizes, int n_in,
                              void* d_out, int out_size) {
    const float* x   = (const float*)d_in[0];
    const float* eps = (const float*)d_in[1];
    const float* wm  = (const float*)d_in[2];
    const float* ws  = (const float*)d_in[3];
    float* out = (float*)d_out;

    void* fp = nullptr;
    cudaGetSymbolAddress(&fp, g_flags);
    cudaMemsetAsync(fp, 0, sizeof(int) * 16);

    cudaFuncSetAttribute(fused_kernel,
                         cudaFuncAttributeMaxDynamicSharedMemorySize,
                         FUSED_SMEM);
    fused_kernel<<<GRID_TOTAL, 256, FUSED_SMEM>>>(
        (const float4*)x, (const float4*)eps,
        (const float4*)wm, (const float4*)ws, out);
}

// round 7
// speedup vs baseline: 1.3086x; 1.3086x over previous
#include <cuda_runtime.h>
#include <cuda_bf16.h>
#include <cstdint>

// out = x @ W,  W = m + softplus(s) * mean_k(eps)
// Fused producer/consumer kernel, 144 co-resident CTAs (<=148 SMs, 1 CTA/SM):
//   CTAs [64,144): producers — split x, build W hi/lo bf16 per k-row pair,
//                  publish per-chunk flags via red.release (no L1 flush).
//   CTAs [0,64):   consumers — 64x256 tile HMMA bf16 3-split GEMM, gated on
//                  chunk flags via single-thread acquire-spin + bar.

#define B_DIM 1024
#define IN_DIM 1024
#define OUT_DIM 1024
#define K_SAMPLES 100
#define PLANE ((IN_DIM * OUT_DIM) / 4)

#define N_CONS 64
#define N_PROD 80
#define GRID_TOTAL (N_CONS + N_PROD)

__device__ __nv_bfloat16 d_xhi[B_DIM * IN_DIM];
__device__ __nv_bfloat16 d_xlo[B_DIM * IN_DIM];
__device__ __nv_bfloat16 d_whi[IN_DIM * OUT_DIM];   // [k][n]
__device__ __nv_bfloat16 d_wlo[IN_DIM * OUT_DIM];
__device__ int g_flags[16];  // [0]=x rows done (1024), [1..8]=W rows per 128-chunk

// ---------------------------------------------------------------------------
__device__ __forceinline__ uint32_t smem_u32(const void* p) {
    uint32_t a;
    asm("{ .reg .u64 t; cvta.to.shared.u64 t, %1; cvt.u32.u64 %0, t; }"
        : "=r"(a) : "l"(p));
    return a;
}
__device__ __forceinline__ void cp16(uint32_t dst, const void* src) {
    asm volatile("cp.async.cg.shared.global [%0], [%1], 16;"
                 :: "r"(dst), "l"(__cvta_generic_to_global(src)) : "memory");
}
__device__ __forceinline__ void ldm4(uint32_t addr, uint32_t r[4]) {
    asm volatile("ldmatrix.sync.aligned.m8n8.x4.shared.b16 {%0,%1,%2,%3}, [%4];"
                 : "=r"(r[0]), "=r"(r[1]), "=r"(r[2]), "=r"(r[3]) : "r"(addr));
}
__device__ __forceinline__ void ldm4t(uint32_t addr, uint32_t r[4]) {
    asm volatile("ldmatrix.sync.aligned.m8n8.x4.trans.shared.b16 {%0,%1,%2,%3}, [%4];"
                 : "=r"(r[0]), "=r"(r[1]), "=r"(r[2]), "=r"(r[3]) : "r"(addr));
}
__device__ __forceinline__ void mma_bf16(float c[4], const uint32_t a[4],
                                         const uint32_t b[2]) {
    asm volatile(
        "mma.sync.aligned.m16n8k16.row.col.f32.bf16.bf16.f32 "
        "{%0,%1,%2,%3}, {%4,%5,%6,%7}, {%8,%9}, {%0,%1,%2,%3};"
        : "+f"(c[0]), "+f"(c[1]), "+f"(c[2]), "+f"(c[3])
        : "r"(a[0]), "r"(a[1]), "r"(a[2]), "r"(a[3]), "r"(b[0]), "r"(b[1]));
}
__device__ __forceinline__ int ld_acq(int* p) {
    int v;
    asm volatile("ld.acquire.gpu.global.s32 %0, [%1];"
                 : "=r"(v) : "l"(p) : "memory");
    return v;
}
__device__ __forceinline__ void red_rel_add(int* p, int v) {
    asm volatile("red.release.gpu.global.add.s32 [%0], %1;"
                 :: "l"(p), "r"(v) : "memory");
}
// Single-thread acquire spin, then block-wide broadcast via bar.
__device__ __forceinline__ void wait_flag_block(int idx, int target) {
    if (threadIdx.x == 0) {
        while (ld_acq(&g_flags[idx]) < target) __nanosleep(64);
    }
    __syncthreads();
}
__device__ __forceinline__ void split_store(__nv_bfloat16* hi, __nv_bfloat16* lo,
                                            int idx4, float4 v) {
    __nv_bfloat16 h0 = __float2bfloat16_rn(v.x);
    __nv_bfloat16 h1 = __float2bfloat16_rn(v.y);
    __nv_bfloat16 h2 = __float2bfloat16_rn(v.z);
    __nv_bfloat16 h3 = __float2bfloat16_rn(v.w);
    __nv_bfloat16 l0 = __float2bfloat16_rn(v.x - __bfloat162float(h0));
    __nv_bfloat16 l1 = __float2bfloat16_rn(v.y - __bfloat162float(h1));
    __nv_bfloat16 l2 = __float2bfloat16_rn(v.z - __bfloat162float(h2));
    __nv_bfloat16 l3 = __float2bfloat16_rn(v.w - __bfloat162float(h3));
    __nv_bfloat162* hp = reinterpret_cast<__nv_bfloat162*>(hi) + idx4 * 2;
    __nv_bfloat162* lp = reinterpret_cast<__nv_bfloat162*>(lo) + idx4 * 2;
    hp[0] = __nv_bfloat162(h0, h1);
    hp[1] = __nv_bfloat162(h2, h3);
    lp[0] = __nv_bfloat162(l0, l1);
    lp[1] = __nv_bfloat162(l2, l3);
}
#define ADD4(a, b) { (a).x += (b).x; (a).y += (b).y; (a).z += (b).z; (a).w += (b).w; }

// ---------------------------------------------------------------------------
// Producer
// ---------------------------------------------------------------------------
__device__ void producer(int p, const float4* __restrict__ x,
                         const float4* __restrict__ eps,
                         const float4* __restrict__ wm,
                         const float4* __restrict__ ws) {
    const int t = threadIdx.x;

    // ---- x split: 2 rows per iteration ----
    int nx = 0;
    for (int rr = 2 * p; rr < B_DIM; rr += 2 * N_PROD) {
        const int i0 = rr * 256 + t;
        float4 v0 = x[i0];
        float4 v1 = x[i0 + 256];
        split_store(d_xhi, d_xlo, i0, v0);
        split_store(d_xhi, d_xlo, i0 + 256, v1);
        nx += 2;
    }
    __syncthreads();
    if (t == 0 && nx) red_rel_add(&g_flags[0], nx);

    // ---- W rows: 2 rows x 10 planes in flight (20 LDG.128 per thread) ----
    const float inv_k = 1.0f / (float)K_SAMPLES;
    for (int rr = 2 * p; rr < IN_DIM; rr += 2 * N_PROD) {
        const int i0 = rr * 256 + t;
        const float4* p0 = eps + i0;
        const float4* p1 = eps + i0 + 256;
        float4 s0 = make_float4(0.f, 0.f, 0.f, 0.f);
        float4 s1 = s0;
#pragma unroll 1
        for (int k = 0; k < K_SAMPLES; k += 10) {
            float4 e0[10], e1[10];
#pragma unroll
            for (int u = 0; u < 10; u++) e0[u] = p0[(k + u) * PLANE];
#pragma unroll
            for (int u = 0; u < 10; u++) e1[u] = p1[(k + u) * PLANE];
#pragma unroll
            for (int u = 0; u < 5; u++) { ADD4(e0[u], e0[u + 5]); ADD4(e1[u], e1[u + 5]); }
            ADD4(e0[0], e0[2]); ADD4(e0[1], e0[3]); ADD4(e0[0], e0[4]);
            ADD4(e0[0], e0[1]); ADD4(s0, e0[0]);
            ADD4(e1[0], e1[2]); ADD4(e1[1], e1[3]); ADD4(e1[0], e1[4]);
            ADD4(e1[0], e1[1]); ADD4(s1, e1[0]);
        }

#pragma unroll
        for (int half = 0; half < 2; half++) {
            const int idx = i0 + half * 256;
            const float4 sv = half ? s1 : s0;
            float4 m4 = wm[idx];
            float4 s4 = ws[idx];
            float sp_x = fmaxf(s4.x, 0.f) + log1pf(expf(-fabsf(s4.x)));
            float sp_y = fmaxf(s4.y, 0.f) + log1pf(expf(-fabsf(s4.y)));
            float sp_z = fmaxf(s4.z, 0.f) + log1pf(expf(-fabsf(s4.z)));
            float sp_w = fmaxf(s4.w, 0.f) + log1pf(expf(-fabsf(s4.w)));
            float4 w4;
            w4.x = fmaf(sp_x, sv.x * inv_k, m4.x);
            w4.y = fmaf(sp_y, sv.y * inv_k, m4.y);
            w4.z = fmaf(sp_z, sv.z * inv_k, m4.z);
            w4.w = fmaf(sp_w, sv.w * inv_k, m4.w);
            split_store(d_whi, d_wlo, idx, w4);
        }

        __syncthreads();                          // all stores for rr, rr+1 done
        if (t == 0) red_rel_add(&g_flags[1 + (rr >> 7)], 2);
    }
}

// ---------------------------------------------------------------------------
// Consumer: 64x256 tile, BKT=32, 3-stage cp.async, chunk-gated
// ---------------------------------------------------------------------------
#define BM 64
#define BN 256
#define BKT 32
#define NKT (IN_DIM / BKT)            // 32 (4 per chunk)
#define NSTAGE 3
#define RSA 80
#define RSB 528
#define OFF_AH 0
#define OFF_AL (BM * RSA)
#define OFF_BH (2 * BM * RSA)
#define OFF_BL (OFF_BH + BKT * RSB)
#define STAGE_BYTES (OFF_BH + 2 * BKT * RSB)   // 44032
#define FUSED_SMEM (NSTAGE * STAGE_BYTES)      // 132096

__device__ __forceinline__ void load_stage(uint32_t st, int bm, int bn,
                                           int k0, int tid) {
    {
        const int row = tid >> 2;
        const int ch = tid & 3;
        const int gk = k0 + ch * 8;
        cp16(st + OFF_AH + row * RSA + ch * 16, d_xhi + (bm + row) * IN_DIM + gk);
        cp16(st + OFF_AL + row * RSA + ch * 16, d_xlo + (bm + row) * IN_DIM + gk);
    }
    {
        const int row = tid >> 3;
        const int ch = tid & 7;
        const __nv_bfloat16* sh = d_whi + (k0 + row) * OUT_DIM + bn;
        const __nv_bfloat16* sl = d_wlo + (k0 + row) * OUT_DIM + bn;
#pragma unroll
        for (int i = 0; i < 4; i++) {
            const int c = ch + 8 * i;
            cp16(st + OFF_BH + row * RSB + c * 16, sh + c * 8);
            cp16(st + OFF_BL + row * RSB + c * 16, sl + c * 8);
        }
    }
}

__device__ void consumer(int cid, float* __restrict__ out, char* smem) {
    const uint32_t sbase = smem_u32(smem);
    const int tid = threadIdx.x;
    const int lane = tid & 31;
    const int wid = tid >> 5;
    const int wm = wid & 1;
    const int wn = wid >> 1;

    const int bm = (cid >> 2) * BM;
    const int bn = (cid & 3) * BN;

    float acc[2][8][4];
#pragma unroll
    for (int i = 0; i < 2; i++)
#pragma unroll
        for (int j = 0; j < 8; j++)
#pragma unroll
            for (int k = 0; k < 4; k++) acc[i][j][k] = 0.f;

    const int ar = lane & 15;
    const int ak = (lane >> 4) * 8;
    const int bkr = (lane & 7) + ((lane >> 3) & 1) * 8;
    const int bnc = (lane >> 4) * 8;

    wait_flag_block(0, B_DIM);        // x fully split
    wait_flag_block(1, 128);          // W chunk 0 ready
    int ready = 0;

#pragma unroll
    for (int s = 0; s < NSTAGE - 1; s++) {
        load_stage(sbase + s * STAGE_BYTES, bm, bn, s * BKT, tid);
        asm volatile("cp.async.commit_group;" ::: "memory");
    }

#pragma unroll 1
    for (int t = 0; t < NKT; ++t) {
        if (t <= NKT - NSTAGE)
            asm volatile("cp.async.wait_group %0;" :: "n"(NSTAGE - 2) : "memory");
        else
            asm volatile("cp.async.wait_group 0;" ::: "memory");
        __syncthreads();

        if (t + NSTAGE - 1 < NKT) {
            const int c = (t + NSTAGE - 1) >> 2;
            if (c > ready) { wait_flag_block(1 + c, 128); ready = c; }
            load_stage(sbase + ((t + NSTAGE - 1) % NSTAGE) * STAGE_BYTES,
                       bm, bn, (t + NSTAGE - 1) * BKT, tid);
            asm volatile("cp.async.commit_group;" ::: "memory");
        }

        const uint32_t st = sbase + (t % NSTAGE) * STAGE_BYTES;

#pragma unroll
        for (int ks = 0; ks < 2; ks++) {
            uint32_t ah[2][4], al[2][4], bh[8][2], bl[8][2];
#pragma unroll
            for (int mh = 0; mh < 2; mh++) {
                const int row = wm * 32 + mh * 16 + ar;
                const uint32_t ad = st + OFF_AH + row * RSA + (ks * 16 + ak) * 2;
                ldm4(ad, ah[mh]);
                ldm4(ad + (OFF_AL - OFF_AH), al[mh]);
            }
#pragma unroll
            for (int q = 0; q < 4; q++) {
                const int krow = ks * 16 + bkr;
                const int ncol = wn * 64 + q * 16 + bnc;
                const uint32_t bd = st + OFF_BH + krow * RSB + ncol * 2;
                uint32_t tmp[4];
                ldm4t(bd, tmp);
                bh[2 * q][0] = tmp[0]; bh[2 * q][1] = tmp[1];
                bh[2 * q + 1][0] = tmp[2]; bh[2 * q + 1][1] = tmp[3];
                ldm4t(bd + (OFF_BL - OFF_BH), tmp);
                bl[2 * q][0] = tmp[0]; bl[2 * q][1] = tmp[1];
                bl[2 * q + 1][0] = tmp[2]; bl[2 * q + 1][1] = tmp[3];
            }
#pragma unroll
            for (int mh = 0; mh < 2; mh++)
#pragma unroll
                for (int nf = 0; nf < 8; nf++) {
                    mma_bf16(acc[mh][nf], ah[mh], bh[nf]);
                    mma_bf16(acc[mh][nf], ah[mh], bl[nf]);
                    mma_bf16(acc[mh][nf], al[mh], bh[nf]);
                }
        }
    }

    const int crow = lane >> 2;
    const int ccol = (lane & 3) * 2;
#pragma unroll
    for (int mh = 0; mh < 2; mh++) {
#pragma unroll
        for (int nf = 0; nf < 8; nf++) {
            const int row = bm + wm * 32 + mh * 16 + crow;
            const int col = bn + wn * 64 + nf * 8 + ccol;
            *reinterpret_cast<float2*>(&out[row * OUT_DIM + col]) =
                make_float2(acc[mh][nf][0], acc[mh][nf][1]);
            *reinterpret_cast<float2*>(&out[(row + 8) * OUT_DIM + col]) =
                make_float2(acc[mh][nf][2], acc[mh][nf][3]);
        }
    }
}

// ---------------------------------------------------------------------------
__global__ __launch_bounds__(256, 1)
void fused_kernel(const float4* __restrict__ x, const float4* __restrict__ eps,
                  const float4* __restrict__ wm, const float4* __restrict__ ws,
                  float* __restrict__ out) {
    extern __shared__ char smem[];
    if (blockIdx.x < N_CONS)
        consumer(blockIdx.x, out, smem);
    else
        producer(blockIdx.x - N_CONS, x, eps, wm, ws);
}

extern "C" void kernel_launch(void* const* d_in, const int* in_sizes, int n_in,
                              void* d_out, int out_size) {
    const float* x   = (const float*)d_in[0];
    const float* eps = (const float*)d_in[1];
    const float* wm  = (const float*)d_in[2];
    const float* ws  = (const float*)d_in[3];
    float* out = (float*)d_out;

    void* fp = nullptr;
    cudaGetSymbolAddress(&fp, g_flags);
    cudaMemsetAsync(fp, 0, sizeof(int) * 16);

    cudaFuncSetAttribute(fused_kernel,
                         cudaFuncAttributeMaxDynamicSharedMemorySize,
                         FUSED_SMEM);
    fused_kernel<<<GRID_TOTAL, 256, FUSED_SMEM>>>(
        (const float4*)x, (const float4*)eps,
        (const float4*)wm, (const float4*)ws, out);
}

// round 8
// speedup vs baseline: 1.4342x; 1.0960x over previous
#include <cuda_runtime.h>
#include <cuda_bf16.h>
#include <cstdint>

// out = x @ W,  W = m + softplus(s) * mean_k(eps)
// Fused producer/consumer kernel, 144 co-resident CTAs, 512 threads each:
//   CTAs [64,144): producers — build W hi/lo bf16, 4 k-rows/iter (MLP 20/thread),
//                  publish per-128-row chunk flags via red.release.
//   CTAs [0,64):   consumers — split their x slice, then 64x256 tile GEMM
//                  (16 compute warps, 32x32 warp tiles), chunk-gated.

#define B_DIM 1024
#define IN_DIM 1024
#define OUT_DIM 1024
#define K_SAMPLES 100
#define PLANE ((IN_DIM * OUT_DIM) / 4)

#define N_CONS 64
#define N_PROD 80
#define GRID_TOTAL (N_CONS + N_PROD)
#define NTHREADS 512

__device__ __nv_bfloat16 d_xhi[B_DIM * IN_DIM];
__device__ __nv_bfloat16 d_xlo[B_DIM * IN_DIM];
__device__ __nv_bfloat16 d_whi[IN_DIM * OUT_DIM];   // [k][n]
__device__ __nv_bfloat16 d_wlo[IN_DIM * OUT_DIM];
__device__ int g_flags[16];  // [0]=x rows (1024), [1..8]=W rows per 128-chunk

// ---------------------------------------------------------------------------
__device__ __forceinline__ uint32_t smem_u32(const void* p) {
    uint32_t a;
    asm("{ .reg .u64 t; cvta.to.shared.u64 t, %1; cvt.u32.u64 %0, t; }"
        : "=r"(a) : "l"(p));
    return a;
}
__device__ __forceinline__ void cp16(uint32_t dst, const void* src) {
    asm volatile("cp.async.cg.shared.global [%0], [%1], 16;"
                 :: "r"(dst), "l"(__cvta_generic_to_global(src)) : "memory");
}
__device__ __forceinline__ void ldm4(uint32_t addr, uint32_t r[4]) {
    asm volatile("ldmatrix.sync.aligned.m8n8.x4.shared.b16 {%0,%1,%2,%3}, [%4];"
                 : "=r"(r[0]), "=r"(r[1]), "=r"(r[2]), "=r"(r[3]) : "r"(addr));
}
__device__ __forceinline__ void ldm4t(uint32_t addr, uint32_t r[4]) {
    asm volatile("ldmatrix.sync.aligned.m8n8.x4.trans.shared.b16 {%0,%1,%2,%3}, [%4];"
                 : "=r"(r[0]), "=r"(r[1]), "=r"(r[2]), "=r"(r[3]) : "r"(addr));
}
__device__ __forceinline__ void mma_bf16(float c[4], const uint32_t a[4],
                                         const uint32_t b[2]) {
    asm volatile(
        "mma.sync.aligned.m16n8k16.row.col.f32.bf16.bf16.f32 "
        "{%0,%1,%2,%3}, {%4,%5,%6,%7}, {%8,%9}, {%0,%1,%2,%3};"
        : "+f"(c[0]), "+f"(c[1]), "+f"(c[2]), "+f"(c[3])
        : "r"(a[0]), "r"(a[1]), "r"(a[2]), "r"(a[3]), "r"(b[0]), "r"(b[1]));
}
__device__ __forceinline__ int ld_acq(int* p) {
    int v;
    asm volatile("ld.acquire.gpu.global.s32 %0, [%1];"
                 : "=r"(v) : "l"(p) : "memory");
    return v;
}
__device__ __forceinline__ void red_rel_add(int* p, int v) {
    asm volatile("red.release.gpu.global.add.s32 [%0], %1;"
                 :: "l"(p), "r"(v) : "memory");
}
__device__ __forceinline__ void wait_flag_block(int idx, int target) {
    if (threadIdx.x == 0) {
        while (ld_acq(&g_flags[idx]) < target) __nanosleep(64);
    }
    __syncthreads();
}
__device__ __forceinline__ void split_store(__nv_bfloat16* hi, __nv_bfloat16* lo,
                                            int idx4, float4 v) {
    __nv_bfloat16 h0 = __float2bfloat16_rn(v.x);
    __nv_bfloat16 h1 = __float2bfloat16_rn(v.y);
    __nv_bfloat16 h2 = __float2bfloat16_rn(v.z);
    __nv_bfloat16 h3 = __float2bfloat16_rn(v.w);
    __nv_bfloat16 l0 = __float2bfloat16_rn(v.x - __bfloat162float(h0));
    __nv_bfloat16 l1 = __float2bfloat16_rn(v.y - __bfloat162float(h1));
    __nv_bfloat16 l2 = __float2bfloat16_rn(v.z - __bfloat162float(h2));
    __nv_bfloat16 l3 = __float2bfloat16_rn(v.w - __bfloat162float(h3));
    __nv_bfloat162* hp = reinterpret_cast<__nv_bfloat162*>(hi) + idx4 * 2;
    __nv_bfloat162* lp = reinterpret_cast<__nv_bfloat162*>(lo) + idx4 * 2;
    hp[0] = __nv_bfloat162(h0, h1);
    hp[1] = __nv_bfloat162(h2, h3);
    lp[0] = __nv_bfloat162(l0, l1);
    lp[1] = __nv_bfloat162(l2, l3);
}
#define ADD4(a, b) { (a).x += (b).x; (a).y += (b).y; (a).z += (b).z; (a).w += (b).w; }

__device__ __forceinline__ void finalize_w(int idx, float4 sv,
                                           const float4* wm, const float4* ws) {
    const float inv_k = 1.0f / (float)K_SAMPLES;
    float4 m4 = wm[idx];
    float4 s4 = ws[idx];
    float sp_x = fmaxf(s4.x, 0.f) + log1pf(expf(-fabsf(s4.x)));
    float sp_y = fmaxf(s4.y, 0.f) + log1pf(expf(-fabsf(s4.y)));
    float sp_z = fmaxf(s4.z, 0.f) + log1pf(expf(-fabsf(s4.z)));
    float sp_w = fmaxf(s4.w, 0.f) + log1pf(expf(-fabsf(s4.w)));
    float4 w4;
    w4.x = fmaf(sp_x, sv.x * inv_k, m4.x);
    w4.y = fmaf(sp_y, sv.y * inv_k, m4.y);
    w4.z = fmaf(sp_z, sv.z * inv_k, m4.z);
    w4.w = fmaf(sp_w, sv.w * inv_k, m4.w);
    split_store(d_whi, d_wlo, idx, w4);
}

// ---------------------------------------------------------------------------
// Producer: 4 k-rows per iteration, 2 elements x 10 planes per thread in flight
// ---------------------------------------------------------------------------
__device__ void producer(int p, const float4* __restrict__ eps,
                         const float4* __restrict__ wm,
                         const float4* __restrict__ ws) {
    const int t = threadIdx.x;

    for (int rr = 4 * p; rr < IN_DIM; rr += 4 * N_PROD) {
        const int i0 = rr * 256 + t;        // covers rows rr, rr+1
        const int i1 = i0 + 512;            // covers rows rr+2, rr+3
        const float4* p0 = eps + i0;
        const float4* p1 = eps + i1;
        float4 s0 = make_float4(0.f, 0.f, 0.f, 0.f);
        float4 s1 = s0;
#pragma unroll 1
        for (int k = 0; k < K_SAMPLES; k += 10) {
            float4 e0[10], e1[10];
#pragma unroll
            for (int u = 0; u < 10; u++) e0[u] = p0[(k + u) * PLANE];
#pragma unroll
            for (int u = 0; u < 10; u++) e1[u] = p1[(k + u) * PLANE];
#pragma unroll
            for (int u = 0; u < 5; u++) { ADD4(e0[u], e0[u + 5]); ADD4(e1[u], e1[u + 5]); }
            ADD4(e0[0], e0[2]); ADD4(e0[1], e0[3]); ADD4(e0[0], e0[4]);
            ADD4(e0[0], e0[1]); ADD4(s0, e0[0]);
            ADD4(e1[0], e1[2]); ADD4(e1[1], e1[3]); ADD4(e1[0], e1[4]);
            ADD4(e1[0], e1[1]); ADD4(s1, e1[0]);
        }
        finalize_w(i0, s0, wm, ws);
        finalize_w(i1, s1, wm, ws);

        __syncthreads();                      // all 4 rows' stores done
        if (t == 0) red_rel_add(&g_flags[1 + (rr >> 7)], 4);
    }
}

// ---------------------------------------------------------------------------
// Consumer: 64x256 tile, 16 compute warps (2x8 grid, 32x32 warp tiles),
// BKT=32, 3-stage cp.async, chunk-gated.
// ---------------------------------------------------------------------------
#define BM 64
#define BN 256
#define BKT 32
#define NKT (IN_DIM / BKT)            // 32 (4 per chunk)
#define NSTAGE 3
#define RSA 80
#define RSB 528
#define OFF_AH 0
#define OFF_AL (BM * RSA)
#define OFF_BH (2 * BM * RSA)
#define OFF_BL (OFF_BH + BKT * RSB)
#define STAGE_BYTES (OFF_BH + 2 * BKT * RSB)   // 44032
#define FUSED_SMEM (NSTAGE * STAGE_BYTES)      // 132096

__device__ __forceinline__ void load_stage(uint32_t st, int bm, int bn,
                                           int k0, int tid) {
    {   // A: hi+lo, 64 rows x 4 chunks = 512 cp, one per thread
        const int mat = tid >> 8;             // 0 hi, 1 lo
        const int r = (tid >> 2) & 63;
        const int ch = tid & 3;
        const __nv_bfloat16* src = (mat ? d_xlo : d_xhi)
                                 + (bm + r) * IN_DIM + k0 + ch * 8;
        cp16(st + (mat ? OFF_AL : OFF_AH) + r * RSA + ch * 16, src);
    }
    {   // B: hi+lo, 32 rows x 32 chunks each = 2048 cp, four per thread
        const int row = tid >> 4;             // 0..31
        const int ch = tid & 15;              // chunks ch, ch+16
        const __nv_bfloat16* sh = d_whi + (k0 + row) * OUT_DIM + bn;
        const __nv_bfloat16* sl = d_wlo + (k0 + row) * OUT_DIM + bn;
        cp16(st + OFF_BH + row * RSB + ch * 16,        sh + ch * 8);
        cp16(st + OFF_BH + row * RSB + (ch + 16) * 16, sh + (ch + 16) * 8);
        cp16(st + OFF_BL + row * RSB + ch * 16,        sl + ch * 8);
        cp16(st + OFF_BL + row * RSB + (ch + 16) * 16, sl + (ch + 16) * 8);
    }
}

__device__ void consumer(int cid, const float4* __restrict__ x,
                         float* __restrict__ out, char* smem) {
    const uint32_t sbase = smem_u32(smem);
    const int tid = threadIdx.x;
    const int lane = tid & 31;
    const int wid = tid >> 5;
    const int wm = wid & 1;          // 32-row half
    const int wn = wid >> 1;         // 0..7, 32-col slice

    const int bm = (cid >> 2) * BM;
    const int bn = (cid & 3) * BN;

    // ---- Phase 0: split x rows [cid*16, cid*16+16) ----
    {
        const int base = cid * 16 * 256;
#pragma unroll
        for (int i = 0; i < 8; i++) {
            const int idx = base + i * 512 + tid;
            split_store(d_xhi, d_xlo, idx, x[idx]);
        }
        __syncthreads();
        if (tid == 0) red_rel_add(&g_flags[0], 16);
    }

    float acc[2][4][4];
#pragma unroll
    for (int i = 0; i < 2; i++)
#pragma unroll
        for (int j = 0; j < 4; j++)
#pragma unroll
            for (int k = 0; k < 4; k++) acc[i][j][k] = 0.f;

    const int ar = lane & 15;
    const int ak = (lane >> 4) * 8;
    const int bkr = (lane & 7) + ((lane >> 3) & 1) * 8;
    const int bnc = (lane >> 4) * 8;

    wait_flag_block(0, B_DIM);        // all x split
    wait_flag_block(1, 128);          // W chunk 0 ready
    int ready = 0;

#pragma unroll
    for (int s = 0; s < NSTAGE - 1; s++) {
        load_stage(sbase + s * STAGE_BYTES, bm, bn, s * BKT, tid);
        asm volatile("cp.async.commit_group;" ::: "memory");
    }

#pragma unroll 1
    for (int t = 0; t < NKT; ++t) {
        if (t <= NKT - NSTAGE)
            asm volatile("cp.async.wait_group %0;" :: "n"(NSTAGE - 2) : "memory");
        else
            asm volatile("cp.async.wait_group 0;" ::: "memory");
        __syncthreads();

        if (t + NSTAGE - 1 < NKT) {
            const int c = (t + NSTAGE - 1) >> 2;
            if (c > ready) { wait_flag_block(1 + c, 128); ready = c; }
            load_stage(sbase + ((t + NSTAGE - 1) % NSTAGE) * STAGE_BYTES,
                       bm, bn, (t + NSTAGE - 1) * BKT, tid);
            asm volatile("cp.async.commit_group;" ::: "memory");
        }

        const uint32_t st = sbase + (t % NSTAGE) * STAGE_BYTES;

#pragma unroll
        for (int ks = 0; ks < 2; ks++) {
            uint32_t ah[2][4], al[2][4], bh[4][2], bl[4][2];
#pragma unroll
            for (int mh = 0; mh < 2; mh++) {
                const int row = wm * 32 + mh * 16 + ar;
                const uint32_t ad = st + OFF_AH + row * RSA + (ks * 16 + ak) * 2;
                ldm4(ad, ah[mh]);
                ldm4(ad + (OFF_AL - OFF_AH), al[mh]);
            }
#pragma unroll
            for (int q = 0; q < 2; q++) {
                const int krow = ks * 16 + bkr;
                const int ncol = wn * 32 + q * 16 + bnc;
                const uint32_t bd = st + OFF_BH + krow * RSB + ncol * 2;
                uint32_t tmp[4];
                ldm4t(bd, tmp);
                bh[2 * q][0] = tmp[0]; bh[2 * q][1] = tmp[1];
                bh[2 * q + 1][0] = tmp[2]; bh[2 * q + 1][1] = tmp[3];
                ldm4t(bd + (OFF_BL - OFF_BH), tmp);
                bl[2 * q][0] = tmp[0]; bl[2 * q][1] = tmp[1];
                bl[2 * q + 1][0] = tmp[2]; bl[2 * q + 1][1] = tmp[3];
            }
#pragma unroll
            for (int mh = 0; mh < 2; mh++)
#pragma unroll
                for (int nf = 0; nf < 4; nf++) {
                    mma_bf16(acc[mh][nf], ah[mh], bh[nf]);
                    mma_bf16(acc[mh][nf], ah[mh], bl[nf]);
                    mma_bf16(acc[mh][nf], al[mh], bh[nf]);
                }
        }
    }

    const int crow = lane >> 2;
    const int ccol = (lane & 3) * 2;
#pragma unroll
    for (int mh = 0; mh < 2; mh++) {
#pragma unroll
        for (int nf = 0; nf < 4; nf++) {
            const int row = bm + wm * 32 + mh * 16 + crow;
            const int col = bn + wn * 32 + nf * 8 + ccol;
            *reinterpret_cast<float2*>(&out[row * OUT_DIM + col]) =
                make_float2(acc[mh][nf][0], acc[mh][nf][1]);
            *reinterpret_cast<float2*>(&out[(row + 8) * OUT_DIM + col]) =
                make_float2(acc[mh][nf][2], acc[mh][nf][3]);
        }
    }
}

// ---------------------------------------------------------------------------
__global__ __launch_bounds__(NTHREADS, 1)
void fused_kernel(const float4* __restrict__ x, const float4* __restrict__ eps,
                  const float4* __restrict__ wm, const float4* __restrict__ ws,
                  float* __restrict__ out) {
    extern __shared__ char smem[];
    if (blockIdx.x < N_CONS)
        consumer(blockIdx.x, x, out, smem);
    else
        producer(blockIdx.x - N_CONS, eps, wm, ws);
}

extern "C" void kernel_launch(void* const* d_in, const int* in_sizes, int n_in,
                              void* d_out, int out_size) {
    const float* x   = (const float*)d_in[0];
    const float* eps = (const float*)d_in[1];
    const float* wm  = (const float*)d_in[2];
    const float* ws  = (const float*)d_in[3];
    float* out = (float*)d_out;

    void* fp = nullptr;
    cudaGetSymbolAddress(&fp, g_flags);
    cudaMemsetAsync(fp, 0, sizeof(int) * 16);

    cudaFuncSetAttribute(fused_kernel,
                         cudaFuncAttributeMaxDynamicSharedMemorySize,
                         FUSED_SMEM);
    fused_kernel<<<GRID_TOTAL, NTHREADS, FUSED_SMEM>>>(
        (const float4*)x, (const float4*)eps,
        (const float4*)wm, (const float4*)ws, out);
}